// round 16
// baseline (speedup 1.0000x reference)
#include <cuda_runtime.h>
#include <cuda_bf16.h>
#include <cuda_fp16.h>
#include <cstdint>
#include <math.h>

#define NN 50000
#define EE 600000
#define D_IN 16
#define DD 128
#define HH 4
#define DHH 32
#define LL 4
#define DFF 512
#define D_OUT 3

// ---------------- scratch ----------------
__device__ float g_x[NN * DD];
__device__ float g_qkv[NN * 384];
__device__ __nv_bfloat16 g_hhi[NN * DD], g_hlo[NN * DD];
__device__ int g_cnt[NN];
__device__ int g_cur[NN];
__device__ int g_rowptr[NN + 1];
__device__ int g_csr_snd[EE];

__device__ __nv_bfloat16 wb_enc_hi[DD * DD], wb_enc_lo[DD * DD];
__device__ __nv_bfloat16 wb_qkv_hi[LL * 384 * DD], wb_qkv_lo[LL * 384 * DD];
__device__ __nv_bfloat16 wb_o_hi[LL * DD * DD], wb_o_lo[LL * DD * DD];
__device__ __half wh_f1[LL * DD * DFF];
__device__ __half wh_f2[LL * DFF * DD];

// ---------------- helpers ----------------
__device__ __forceinline__ void hmma_bf16(float* c, const uint32_t* a, uint32_t b0, uint32_t b1) {
    asm volatile(
        "mma.sync.aligned.m16n8k16.row.col.f32.bf16.bf16.f32 "
        "{%0,%1,%2,%3}, {%4,%5,%6,%7}, {%8,%9}, {%0,%1,%2,%3};"
        : "+f"(c[0]), "+f"(c[1]), "+f"(c[2]), "+f"(c[3])
        : "r"(a[0]), "r"(a[1]), "r"(a[2]), "r"(a[3]), "r"(b0), "r"(b1));
}
__device__ __forceinline__ void hmma_f16(float* c, const uint32_t* a, uint32_t b0, uint32_t b1) {
    asm volatile(
        "mma.sync.aligned.m16n8k16.row.col.f32.f16.f16.f32 "
        "{%0,%1,%2,%3}, {%4,%5,%6,%7}, {%8,%9}, {%0,%1,%2,%3};"
        : "+f"(c[0]), "+f"(c[1]), "+f"(c[2]), "+f"(c[3])
        : "r"(a[0]), "r"(a[1]), "r"(a[2]), "r"(a[3]), "r"(b0), "r"(b1));
}
#define LDMX4(r0, r1, r2, r3, addr) \
    asm volatile("ldmatrix.sync.aligned.m8n8.x4.shared.b16 {%0,%1,%2,%3}, [%4];" \
                 : "=r"(r0), "=r"(r1), "=r"(r2), "=r"(r3) : "r"(addr))

__device__ __forceinline__ void split2(float x, float y, uint32_t& hi, uint32_t& lo) {
    __nv_bfloat16 hx = __float2bfloat16(x);
    __nv_bfloat16 hy = __float2bfloat16(y);
    __nv_bfloat16 lx = __float2bfloat16(x - __bfloat162float(hx));
    __nv_bfloat16 ly = __float2bfloat16(y - __bfloat162float(hy));
    __nv_bfloat162 hp = __halves2bfloat162(hx, hy);
    __nv_bfloat162 lp = __halves2bfloat162(lx, ly);
    hi = *(uint32_t*)&hp;
    lo = *(uint32_t*)&lp;
}
__device__ __forceinline__ void split2h(float x, float y, uint32_t& hi, uint32_t& lo) {
    __half hx = __float2half(x);
    __half hy = __float2half(y);
    __half lx = __float2half(x - __half2float(hx));
    __half ly = __float2half(y - __half2float(hy));
    __half2 hp = __halves2half2(hx, hy);
    __half2 lp = __halves2half2(lx, ly);
    hi = *(uint32_t*)&hp;
    lo = *(uint32_t*)&lp;
}
__device__ __forceinline__ uint32_t smem_u32(const void* p) {
    uint32_t a;
    asm("{ .reg .u64 t; cvta.to.shared.u64 t, %1; cvt.u32.u64 %0, t; }" : "=r"(a) : "l"(p));
    return a;
}
__device__ __forceinline__ void cp16(uint32_t dst, const void* src, int sz) {
    asm volatile("cp.async.ca.shared.global [%0], [%1], 16, %2;" :: "r"(dst), "l"(src), "r"(sz));
}

// ---------------- weight split kernels ----------------
__global__ void split_w_kernel(const float* __restrict__ W, __nv_bfloat16* __restrict__ hi,
                               __nv_bfloat16* __restrict__ lo, int K, int M, int total,
                               int out_cols, int col_off) {
    int idx = blockIdx.x * blockDim.x + threadIdx.x;
    if (idx >= total) return;
    int km = K * M;
    int mat = idx / km;
    int rem = idx - mat * km;
    int r = rem / M, c = rem - r * M;
    float w = W[idx];
    __nv_bfloat16 h = __float2bfloat16(w);
    __nv_bfloat16 l = __float2bfloat16(w - __bfloat162float(h));
    int dst = mat * (out_cols * K) + (c + col_off) * K + r;
    hi[dst] = h;
    lo[dst] = l;
}
__global__ void split_w_qkv_kernel(const float* __restrict__ Wq, const float* __restrict__ Wk,
                                   const float* __restrict__ Wv,
                                   __nv_bfloat16* __restrict__ hi, __nv_bfloat16* __restrict__ lo) {
    int idx = blockIdx.x * blockDim.x + threadIdx.x;
    const int per = LL * DD * DD;
    if (idx >= 3 * per) return;
    int which = idx / per;
    int rem0 = idx - which * per;
    const float* W = (which == 0) ? Wq : (which == 1) ? Wk : Wv;
    int km = DD * DD;
    int mat = rem0 / km;
    int rem = rem0 - mat * km;
    int r = rem / DD, c = rem - r * DD;
    float w = W[rem0];
    __nv_bfloat16 h = __float2bfloat16(w);
    __nv_bfloat16 l = __float2bfloat16(w - __bfloat162float(h));
    int dst = mat * (384 * DD) + (c + which * 128) * DD + r;
    hi[dst] = h;
    lo[dst] = l;
}
__global__ void split_w_h_kernel(const float* __restrict__ W, __half* __restrict__ out,
                                 int K, int M, int total) {
    int idx = blockIdx.x * blockDim.x + threadIdx.x;
    if (idx >= total) return;
    int km = K * M;
    int mat = idx / km;
    int rem = idx - mat * km;
    int r = rem / M, c = rem - r * M;
    out[mat * km + c * K + r] = __float2half(W[idx]);
}

// ---------------- bf16x3 GEMM: cp.async double-buffer + ldmatrix ----------------
template <int K, int MOUT, bool RELU, bool ADD, bool OSPLIT>
__global__ void __launch_bounds__(256, 2) gemm_db(const __nv_bfloat16* __restrict__ Ahi,
                                                  const __nv_bfloat16* __restrict__ Alo,
                                                  const __nv_bfloat16* __restrict__ Bhi,
                                                  const __nv_bfloat16* __restrict__ Blo,
                                                  const float* __restrict__ bias,
                                                  float* __restrict__ C,
                                                  __nv_bfloat16* __restrict__ Ohi,
                                                  __nv_bfloat16* __restrict__ Olo, int n) {
    extern __shared__ uint32_t S[];
    constexpr int NCH = K / 32;
    constexpr int PL4 = 2560 * 4;
    constexpr int BUF4 = 10240 * 4;

    int tid = threadIdx.x;
    int l = tid & 31;
    int wm = (tid >> 5) & 3;
    int wn = tid >> 7;
    int row0 = blockIdx.x * 128, col0 = blockIdx.y * 128;
    uint32_t sbase = smem_u32(S);

    float acc[2][8][4];
#pragma unroll
    for (int a = 0; a < 2; a++)
#pragma unroll
        for (int b = 0; b < 8; b++)
#pragma unroll
            for (int c = 0; c < 4; c++) acc[a][b][c] = 0.f;

    auto stage = [&](int b, int k0) {
#pragma unroll
        for (int i = 0; i < 8; i++) {
            int plane = i >> 1;
            int cc = (i & 1) * 256 + tid;
            int row = cc >> 2, part = cc & 3;
            uint32_t daddr = sbase + (uint32_t)(b * BUF4 + plane * PL4 + (row * 20 + part * 4) * 4);
            if (plane < 2) {
                int grow = row0 + row;
                int ok = grow < n;
                const __nv_bfloat16* base = (plane == 0) ? Ahi : Alo;
                const void* src = base + (size_t)(ok ? grow : 0) * K + k0 + part * 8;
                cp16(daddr, src, ok ? 16 : 0);
            } else {
                const __nv_bfloat16* base = (plane == 2) ? Bhi : Blo;
                const void* src = base + (size_t)(col0 + row) * K + k0 + part * 8;
                cp16(daddr, src, 16);
            }
        }
    };

    const uint32_t aoff = (uint32_t)(((wm * 32 + (l & 15)) * 20 + (l >> 4) * 4) * 4);
    const uint32_t boff = (uint32_t)(((wn * 64 + (l & 7) + ((l >> 4) << 3)) * 20 + ((l >> 3) & 1) * 4) * 4);

    stage(0, 0);
    asm volatile("cp.async.commit_group;");

    for (int ch = 0; ch < NCH; ch++) {
        if (ch + 1 < NCH) {
            stage((ch + 1) & 1, (ch + 1) * 32);
            asm volatile("cp.async.commit_group;");
            asm volatile("cp.async.wait_group 1;");
        } else {
            asm volatile("cp.async.wait_group 0;");
        }
        __syncthreads();

        uint32_t base = sbase + (ch & 1) * BUF4;

#pragma unroll
        for (int ks = 0; ks < 2; ks++) {
            uint32_t kb = (uint32_t)(ks * 32);
            uint32_t ah[2][4], al[2][4];
            LDMX4(ah[0][0], ah[0][1], ah[0][2], ah[0][3], base + aoff + kb);
            LDMX4(ah[1][0], ah[1][1], ah[1][2], ah[1][3], base + aoff + 16 * 80 + kb);
            LDMX4(al[0][0], al[0][1], al[0][2], al[0][3], base + PL4 + aoff + kb);
            LDMX4(al[1][0], al[1][1], al[1][2], al[1][3], base + PL4 + aoff + 16 * 80 + kb);
#pragma unroll
            for (int tn2 = 0; tn2 < 4; tn2++) {
                uint32_t bh[4], bl[4];
                LDMX4(bh[0], bh[1], bh[2], bh[3], base + 2 * PL4 + boff + tn2 * 16 * 80 + kb);
                LDMX4(bl[0], bl[1], bl[2], bl[3], base + 3 * PL4 + boff + tn2 * 16 * 80 + kb);
#pragma unroll
                for (int sub = 0; sub < 2; sub++) {
                    int tn = 2 * tn2 + sub;
#pragma unroll
                    for (int tm = 0; tm < 2; tm++) {
                        hmma_bf16(acc[tm][tn], ah[tm], bh[2 * sub], bh[2 * sub + 1]);
                        hmma_bf16(acc[tm][tn], ah[tm], bl[2 * sub], bl[2 * sub + 1]);
                        hmma_bf16(acc[tm][tn], al[tm], bh[2 * sub], bh[2 * sub + 1]);
                    }
                }
            }
        }
        __syncthreads();
    }

#pragma unroll
    for (int tm = 0; tm < 2; tm++) {
#pragma unroll
        for (int tn = 0; tn < 8; tn++) {
            int row = row0 + wm * 32 + tm * 16 + (l >> 2);
            int col = col0 + wn * 64 + tn * 8 + (l & 3) * 2;
            float b0 = 0.f, b1 = 0.f;
            if (bias) { b0 = bias[col]; b1 = bias[col + 1]; }
#pragma unroll
            for (int half = 0; half < 2; half++) {
                int r = row + half * 8;
                if (r < n) {
                    float v0 = acc[tm][tn][half * 2 + 0] + b0;
                    float v1 = acc[tm][tn][half * 2 + 1] + b1;
                    if (RELU) { v0 = fmaxf(v0, 0.f); v1 = fmaxf(v1, 0.f); }
                    if (OSPLIT) {
                        uint32_t hi, lo;
                        split2(v0, v1, hi, lo);
                        *(uint32_t*)(Ohi + (size_t)r * MOUT + col) = hi;
                        *(uint32_t*)(Olo + (size_t)r * MOUT + col) = lo;
                    } else {
                        float2* cp = (float2*)(C + (size_t)r * MOUT + col);
                        if (ADD) {
                            float2 old = *cp;
                            v0 += old.x; v1 += old.y;
                        }
                        *cp = make_float2(v0, v1);
                    }
                }
            }
        }
    }
}

// ---------------- fused LN2 + FFN ----------------
__global__ void __launch_bounds__(256) ffn_fused(const float* __restrict__ X,
                                                 const __half* __restrict__ W1,
                                                 const __half* __restrict__ W2,
                                                 const float* __restrict__ b1,
                                                 const float* __restrict__ b2,
                                                 const float* __restrict__ lns,
                                                 const float* __restrict__ lnb,
                                                 float* __restrict__ C, int n) {
    extern __shared__ __half SH[];
    constexpr int RB = 272;
    const uint32_t sb = smem_u32(SH);
    const uint32_t oAhi = 0, oAlo = 128 * RB, oW1 = 2 * 128 * RB, oW2 = 3 * 128 * RB;
    const uint32_t oMhi = 4 * 128 * RB, oMlo = 5 * 128 * RB;
    const uint32_t oX = oMhi;

    int tid = threadIdx.x;
    int l = tid & 31;
    int wmw = (tid >> 5) & 3;
    int wn = tid >> 7;
    int wid = tid >> 5;
    int row0 = blockIdx.x * 128;

    float acc2[2][8][4];
#pragma unroll
    for (int a = 0; a < 2; a++)
#pragma unroll
        for (int b = 0; b < 8; b++)
#pragma unroll
            for (int c = 0; c < 4; c++) acc2[a][b][c] = 0.f;

#pragma unroll
    for (int i = 0; i < 16; i++) {
        int lin = i * 256 + tid;
        int row = lin >> 5, part = lin & 31;
        int grow = row0 + row;
        int ok = grow < n;
        const void* src = X + (size_t)(ok ? grow : 0) * DD + part * 4;
        cp16(sb + oX + row * 544 + part * 16, src, ok ? 16 : 0);
    }
    asm volatile("cp.async.commit_group;");

    auto stageW = [&](int c) {
#pragma unroll
        for (int i = 0; i < 16; i++) {
            int lin = i * 256 + tid;
            int which = lin >> 11;
            int rem = lin & 2047;
            int row = rem >> 4, part = rem & 15;
            if (which == 0) {
                const void* src = W1 + (size_t)(c * 128 + row) * DD + part * 8;
                cp16(sb + oW1 + row * RB + part * 16, src, 16);
            } else {
                const void* src = W2 + (size_t)row * DFF + c * 128 + part * 8;
                cp16(sb + oW2 + row * RB + part * 16, src, 16);
            }
        }
    };
    stageW(0);
    asm volatile("cp.async.commit_group;");

    asm volatile("cp.async.wait_group 1;");
    __syncthreads();

#pragma unroll
    for (int i = 0; i < 16; i++) {
        int row = wid * 16 + i;
        const float* xr = (const float*)((char*)SH + oX + row * 544);
        float4 v = *(const float4*)(xr + l * 4);
        float sum = v.x + v.y + v.z + v.w;
        float sq = v.x * v.x + v.y * v.y + v.z * v.z + v.w * v.w;
#pragma unroll
        for (int off = 16; off; off >>= 1) {
            sum += __shfl_xor_sync(0xffffffffu, sum, off);
            sq += __shfl_xor_sync(0xffffffffu, sq, off);
        }
        float mu = sum * (1.f / 128.f);
        float var = sq * (1.f / 128.f) - mu * mu;
        float rstd = rsqrtf(var + 1e-5f);
        float4 sv = *(const float4*)(lns + l * 4);
        float4 bv = *(const float4*)(lnb + l * 4);
        float o0 = (v.x - mu) * rstd * sv.x + bv.x;
        float o1 = (v.y - mu) * rstd * sv.y + bv.y;
        float o2 = (v.z - mu) * rstd * sv.z + bv.z;
        float o3 = (v.w - mu) * rstd * sv.w + bv.w;
        uint32_t h0, l0, h1, l1;
        split2h(o0, o1, h0, l0);
        split2h(o2, o3, h1, l1);
        *(uint32_t*)((char*)SH + oAhi + row * RB + l * 8) = h0;
        *(uint32_t*)((char*)SH + oAhi + row * RB + l * 8 + 4) = h1;
        *(uint32_t*)((char*)SH + oAlo + row * RB + l * 8) = l0;
        *(uint32_t*)((char*)SH + oAlo + row * RB + l * 8 + 4) = l1;
    }
    __syncthreads();

    const uint32_t aoff = (uint32_t)((wmw * 32 + (l & 15)) * RB + (l >> 4) * 16);
    const uint32_t boff = (uint32_t)((wn * 64 + (l & 7) + ((l >> 4) << 3)) * RB + ((l >> 3) & 1) * 16);

    for (int c = 0; c < 4; c++) {
        if (c > 0) {
            __syncthreads();
            stageW(c);
            asm volatile("cp.async.commit_group;");
        }
        asm volatile("cp.async.wait_group 0;");
        __syncthreads();

        float acc1[2][8][4];
#pragma unroll
        for (int a = 0; a < 2; a++)
#pragma unroll
            for (int b = 0; b < 8; b++)
#pragma unroll
                for (int q = 0; q < 4; q++) acc1[a][b][q] = 0.f;

#pragma unroll
        for (int ks = 0; ks < 8; ks++) {
            uint32_t kb = (uint32_t)(ks * 32);
            uint32_t ah[2][4], al[2][4];
            LDMX4(ah[0][0], ah[0][1], ah[0][2], ah[0][3], sb + oAhi + aoff + kb);
            LDMX4(ah[1][0], ah[1][1], ah[1][2], ah[1][3], sb + oAhi + aoff + 16 * RB + kb);
            LDMX4(al[0][0], al[0][1], al[0][2], al[0][3], sb + oAlo + aoff + kb);
            LDMX4(al[1][0], al[1][1], al[1][2], al[1][3], sb + oAlo + aoff + 16 * RB + kb);
#pragma unroll
            for (int tn2 = 0; tn2 < 4; tn2++) {
                uint32_t bb[4];
                LDMX4(bb[0], bb[1], bb[2], bb[3], sb + oW1 + boff + tn2 * 16 * RB + kb);
#pragma unroll
                for (int sub = 0; sub < 2; sub++) {
                    int tn = 2 * tn2 + sub;
#pragma unroll
                    for (int tm = 0; tm < 2; tm++) {
                        hmma_f16(acc1[tm][tn], ah[tm], bb[2 * sub], bb[2 * sub + 1]);
                        hmma_f16(acc1[tm][tn], al[tm], bb[2 * sub], bb[2 * sub + 1]);
                    }
                }
            }
        }

#pragma unroll
        for (int tm = 0; tm < 2; tm++) {
#pragma unroll
            for (int tn = 0; tn < 8; tn++) {
                int rloc = wmw * 32 + tm * 16 + (l >> 2);
                int cloc = wn * 64 + tn * 8 + (l & 3) * 2;
                float bb0 = b1[c * 128 + cloc], bb1 = b1[c * 128 + cloc + 1];
#pragma unroll
                for (int half = 0; half < 2; half++) {
                    int rr = rloc + half * 8;
                    float v0 = fmaxf(acc1[tm][tn][half * 2 + 0] + bb0, 0.f);
                    float v1 = fmaxf(acc1[tm][tn][half * 2 + 1] + bb1, 0.f);
                    uint32_t hi, lo;
                    split2h(v0, v1, hi, lo);
                    *(uint32_t*)((char*)SH + oMhi + rr * RB + cloc * 2) = hi;
                    *(uint32_t*)((char*)SH + oMlo + rr * RB + cloc * 2) = lo;
                }
            }
        }
        __syncthreads();

#pragma unroll
        for (int ks = 0; ks < 8; ks++) {
            uint32_t kb = (uint32_t)(ks * 32);
            uint32_t mh[2][4], ml[2][4];
            LDMX4(mh[0][0], mh[0][1], mh[0][2], mh[0][3], sb + oMhi + aoff + kb);
            LDMX4(mh[1][0], mh[1][1], mh[1][2], mh[1][3], sb + oMhi + aoff + 16 * RB + kb);
            LDMX4(ml[0][0], ml[0][1], ml[0][2], ml[0][3], sb + oMlo + aoff + kb);
            LDMX4(ml[1][0], ml[1][1], ml[1][2], ml[1][3], sb + oMlo + aoff + 16 * RB + kb);
#pragma unroll
            for (int tn2 = 0; tn2 < 4; tn2++) {
                uint32_t bb[4];
                LDMX4(bb[0], bb[1], bb[2], bb[3], sb + oW2 + boff + tn2 * 16 * RB + kb);
#pragma unroll
                for (int sub = 0; sub < 2; sub++) {
                    int tn = 2 * tn2 + sub;
#pragma unroll
                    for (int tm = 0; tm < 2; tm++) {
                        hmma_f16(acc2[tm][tn], mh[tm], bb[2 * sub], bb[2 * sub + 1]);
                        hmma_f16(acc2[tm][tn], ml[tm], bb[2 * sub], bb[2 * sub + 1]);
                    }
                }
            }
        }
    }

#pragma unroll
    for (int tm = 0; tm < 2; tm++) {
#pragma unroll
        for (int tn = 0; tn < 8; tn++) {
            int row = row0 + wmw * 32 + tm * 16 + (l >> 2);
            int col = wn * 64 + tn * 8 + (l & 3) * 2;
            float bb0 = b2[col], bb1 = b2[col + 1];
#pragma unroll
            for (int half = 0; half < 2; half++) {
                int r = row + half * 8;
                if (r < n) {
                    float2* cp = (float2*)(C + (size_t)r * DD + col);
                    float2 old = *cp;
                    *cp = make_float2(acc2[tm][tn][half * 2 + 0] + bb0 + old.x,
                                      acc2[tm][tn][half * 2 + 1] + bb1 + old.y);
                }
            }
        }
    }
}

// ---------------- small fp32 GEMM (encoder K=16) -> split bf16 out ----------------
__global__ void __launch_bounds__(256) gemm_small(const float* __restrict__ A,
                                                  const float* __restrict__ W,
                                                  const float* __restrict__ bias,
                                                  __nv_bfloat16* __restrict__ Ohi,
                                                  __nv_bfloat16* __restrict__ Olo, int n) {
    constexpr int K = D_IN, MOUT = DD, BM = 64, BK = 16, TM = 8, TN = 4;
    __shared__ float As[BK][BM + 4];
    __shared__ float Ws[BK][MOUT];
    int row0 = blockIdx.x * BM;
    int tid = threadIdx.x;
    int tx = tid & 31, ty = tid >> 5;
    float acc[TM][TN];
#pragma unroll
    for (int i = 0; i < TM; i++)
#pragma unroll
        for (int j = 0; j < TN; j++) acc[i][j] = 0.f;
    int a_row = tid >> 2, a_kq = (tid & 3) * 4;
    {
        float4 av = make_float4(0.f, 0.f, 0.f, 0.f);
        int grow = row0 + a_row;
        if (grow < n) av = *(const float4*)(A + (size_t)grow * K + a_kq);
        As[a_kq + 0][a_row] = av.x;
        As[a_kq + 1][a_row] = av.y;
        As[a_kq + 2][a_row] = av.z;
        As[a_kq + 3][a_row] = av.w;
#pragma unroll
        for (int i = 0; i < 2; i++) {
            int lin = tid + i * 256;
            int wk = lin >> 5;
            int wc = (lin & 31) * 4;
            *(float4*)&Ws[wk][wc] = *(const float4*)(W + (size_t)wk * MOUT + wc);
        }
        __syncthreads();
#pragma unroll
        for (int kk = 0; kk < BK; kk++) {
            float a[TM], w[TN];
            *(float4*)&a[0] = *(float4*)&As[kk][ty * TM];
            *(float4*)&a[4] = *(float4*)&As[kk][ty * TM + 4];
            *(float4*)&w[0] = *(float4*)&Ws[kk][tx * TN];
#pragma unroll
            for (int i = 0; i < TM; i++)
#pragma unroll
                for (int j = 0; j < TN; j++) acc[i][j] += a[i] * w[j];
        }
    }
#pragma unroll
    for (int i = 0; i < TM; i++) {
        int row = row0 + ty * TM + i;
        if (row < n) {
            float v0 = fmaxf(acc[i][0] + bias[tx * TN + 0], 0.f);
            float v1 = fmaxf(acc[i][1] + bias[tx * TN + 1], 0.f);
            float v2 = fmaxf(acc[i][2] + bias[tx * TN + 2], 0.f);
            float v3 = fmaxf(acc[i][3] + bias[tx * TN + 3], 0.f);
            uint32_t h0, l0, h1, l1;
            split2(v0, v1, h0, l0);
            split2(v2, v3, h1, l1);
            *(uint2*)(Ohi + (size_t)row * MOUT + tx * TN) = make_uint2(h0, h1);
            *(uint2*)(Olo + (size_t)row * MOUT + tx * TN) = make_uint2(l0, l1);
        }
    }
}

// ---------------- LayerNorm -> split bf16 out ----------------
__global__ void ln_kernel(const float* __restrict__ x, const float* __restrict__ s,
                          const float* __restrict__ b, __nv_bfloat16* __restrict__ Ohi,
                          __nv_bfloat16* __restrict__ Olo, int n) {
    int row = blockIdx.x * 8 + (threadIdx.x >> 5);
    if (row >= n) return;
    int lane = threadIdx.x & 31;
    float4 v = *(const float4*)(x + (size_t)row * DD + lane * 4);
    float sum = v.x + v.y + v.z + v.w;
    float sq = v.x * v.x + v.y * v.y + v.z * v.z + v.w * v.w;
#pragma unroll
    for (int off = 16; off; off >>= 1) {
        sum += __shfl_xor_sync(0xffffffffu, sum, off);
        sq += __shfl_xor_sync(0xffffffffu, sq, off);
    }
    float mu = sum * (1.f / 128.f);
    float var = sq * (1.f / 128.f) - mu * mu;
    float rstd = rsqrtf(var + 1e-5f);
    float4 sv = *(const float4*)(s + lane * 4);
    float4 bv = *(const float4*)(b + lane * 4);
    float o0 = (v.x - mu) * rstd * sv.x + bv.x;
    float o1 = (v.y - mu) * rstd * sv.y + bv.y;
    float o2 = (v.z - mu) * rstd * sv.z + bv.z;
    float o3 = (v.w - mu) * rstd * sv.w + bv.w;
    uint32_t h0, l0, h1, l1;
    split2(o0, o1, h0, l0);
    split2(o2, o3, h1, l1);
    *(uint2*)(Ohi + (size_t)row * DD + lane * 4) = make_uint2(h0, h1);
    *(uint2*)(Olo + (size_t)row * DD + lane * 4) = make_uint2(l0, l1);
}

// ---------------- CSR build ----------------
__global__ void zero_cnt_kernel() {
    int i = blockIdx.x * blockDim.x + threadIdx.x;
    if (i < NN) g_cnt[i] = 0;
}
__global__ void hist_kernel(const int* __restrict__ receivers) {
    int e = blockIdx.x * blockDim.x + threadIdx.x;
    if (e < EE) atomicAdd(&g_cnt[receivers[e]], 1);
}
__global__ void scan_kernel() {
    __shared__ int warp_sums[32];
    __shared__ int s_carry;
    int lane = threadIdx.x & 31;
    int wid = threadIdx.x >> 5;
    if (threadIdx.x == 0) s_carry = 0;
    __syncthreads();
    for (int base = 0; base < NN; base += 1024) {
        int i = base + threadIdx.x;
        int v = (i < NN) ? g_cnt[i] : 0;
        int incl = v;
#pragma unroll
        for (int off = 1; off < 32; off <<= 1) {
            int t = __shfl_up_sync(0xffffffffu, incl, off);
            if (lane >= off) incl += t;
        }
        if (lane == 31) warp_sums[wid] = incl;
        __syncthreads();
        if (wid == 0) {
            int ws = warp_sums[lane];
            int wincl = ws;
#pragma unroll
            for (int off = 1; off < 32; off <<= 1) {
                int t = __shfl_up_sync(0xffffffffu, wincl, off);
                if (lane >= off) wincl += t;
            }
            warp_sums[lane] = wincl - ws;
        }
        __syncthreads();
        int total_incl = s_carry + warp_sums[wid] + incl;
        if (i < NN) {
            g_rowptr[i + 1] = total_incl;
            g_cur[i] = total_incl - v;
        }
        __syncthreads();
        if (threadIdx.x == 1023) s_carry = total_incl;
        __syncthreads();
    }
    if (threadIdx.x == 0) g_rowptr[0] = 0;
}
__global__ void scatter_kernel(const int* __restrict__ senders,
                               const int* __restrict__ receivers) {
    int e = blockIdx.x * blockDim.x + threadIdx.x;
    if (e >= EE) return;
    int pos = atomicAdd(&g_cur[receivers[e]], 1);
    g_csr_snd[pos] = senders[e];
}

// ---------------- fused sparse attention (no online-max; scores bounded by LN) ----------------
__global__ void attn_kernel() {
    int warp = (blockIdx.x * blockDim.x + threadIdx.x) >> 5;
    if (warp >= NN) return;
    int lane = threadIdx.x & 31;
    int node = warp;
    int l4 = lane * 4;

    float4 q4 = *(const float4*)(g_qkv + (size_t)node * 384 + l4);
    int beg = g_rowptr[node], end = g_rowptr[node + 1];

    float den = 0.f;
    float4 acc = make_float4(0.f, 0.f, 0.f, 0.f);

    if (beg < end) {
        int snd = g_csr_snd[beg];
        const float* kp = g_qkv + (size_t)snd * 384 + 128;
        float4 k4 = *(const float4*)(kp + l4);
        float4 v4 = *(const float4*)(kp + 128 + l4);
        for (int j = beg; j < end; j++) {
            int snd_n = (j + 1 < end) ? g_csr_snd[j + 1] : snd;
            const float* kpn = g_qkv + (size_t)snd_n * 384 + 128;
            float4 k4n = *(const float4*)(kpn + l4);
            float4 v4n = *(const float4*)(kpn + 128 + l4);

            float d = q4.x * k4.x + q4.y * k4.y + q4.z * k4.z + q4.w * k4.w;
            d += __shfl_xor_sync(0xffffffffu, d, 1);
            d += __shfl_xor_sync(0xffffffffu, d, 2);
            d += __shfl_xor_sync(0xffffffffu, d, 4);
            float a = __expf(d * 0.17677669529663687f);  // 1/sqrt(32); |s| bounded, no max needed
            den += a;
            acc.x = fmaf(a, v4.x, acc.x);
            acc.y = fmaf(a, v4.y, acc.y);
            acc.z = fmaf(a, v4.z, acc.z);
            acc.w = fmaf(a, v4.w, acc.w);
            k4 = k4n; v4 = v4n;
        }
    }
    float inv = 1.f / (den + 1e-9f);
    uint32_t h0, l0, h1, l1;
    split2(acc.x * inv, acc.y * inv, h0, l0);
    split2(acc.z * inv, acc.w * inv, h1, l1);
    *(uint2*)(g_hhi + (size_t)node * DD + l4) = make_uint2(h0, h1);
    *(uint2*)(g_hlo + (size_t)node * DD + l4) = make_uint2(l0, l1);
}

// ---------------- decoder ----------------
__global__ void decode_kernel(const float* __restrict__ x, const float* __restrict__ w1,
                              const float* __restrict__ b1, const float* __restrict__ w2,
                              const float* __restrict__ b2, float* __restrict__ out, int n) {
    int row = blockIdx.x * 4 + (threadIdx.x >> 5);
    if (row >= n) return;
    int lane = threadIdx.x & 31;
    float4 xr = *(const float4*)(x + (size_t)row * DD + lane * 4);
    float t[3];
#pragma unroll
    for (int o = 0; o < 3; o++) {
        float p = xr.x * w1[(lane * 4 + 0) * 3 + o] + xr.y * w1[(lane * 4 + 1) * 3 + o] +
                  xr.z * w1[(lane * 4 + 2) * 3 + o] + xr.w * w1[(lane * 4 + 3) * 3 + o];
#pragma unroll
        for (int off = 16; off; off >>= 1) p += __shfl_down_sync(0xffffffffu, p, off);
        t[o] = p;
    }
    if (lane == 0) {
        float r0 = fmaxf(t[0] + b1[0], 0.f);
        float r1 = fmaxf(t[1] + b1[1], 0.f);
        float r2 = fmaxf(t[2] + b1[2], 0.f);
#pragma unroll
        for (int o2 = 0; o2 < 3; o2++)
            out[row * 3 + o2] = r0 * w2[0 * 3 + o2] + r1 * w2[1 * 3 + o2] + r2 * w2[2 * 3 + o2] + b2[o2];
    }
}

// ---------------- host ----------------
extern "C" void kernel_launch(void* const* d_in, const int* in_sizes, int n_in,
                              void* d_out, int out_size) {
    const float* features = (const float*)d_in[0];
    const int* senders = (const int*)d_in[1];
    const int* receivers = (const int*)d_in[2];
    const float* enc_w1 = (const float*)d_in[3];
    const float* enc_b1 = (const float*)d_in[4];
    const float* enc_w2 = (const float*)d_in[5];
    const float* enc_b2 = (const float*)d_in[6];
    const float* wq = (const float*)d_in[7];
    const float* wk = (const float*)d_in[8];
    const float* wv = (const float*)d_in[9];
    const float* wo = (const float*)d_in[10];
    const float* ln1_s = (const float*)d_in[11];
    const float* ln1_b = (const float*)d_in[12];
    const float* ffn_w1 = (const float*)d_in[13];
    const float* ffn_b1 = (const float*)d_in[14];
    const float* ffn_w2 = (const float*)d_in[15];
    const float* ffn_b2 = (const float*)d_in[16];
    const float* ln2_s = (const float*)d_in[17];
    const float* ln2_b = (const float*)d_in[18];
    const float* dec_w1 = (const float*)d_in[19];
    const float* dec_b1 = (const float*)d_in[20];
    const float* dec_w2 = (const float*)d_in[21];
    const float* dec_b2 = (const float*)d_in[22];
    float* out = (float*)d_out;

    float* x;    cudaGetSymbolAddress((void**)&x, g_x);
    float* qkv;  cudaGetSymbolAddress((void**)&qkv, g_qkv);
    __nv_bfloat16 *hhi, *hlo;
    cudaGetSymbolAddress((void**)&hhi, g_hhi);
    cudaGetSymbolAddress((void**)&hlo, g_hlo);
    __nv_bfloat16 *we_h, *we_l, *wqkv_h, *wqkv_l, *wo_h, *wo_l;
    __half *f1h, *f2h;
    cudaGetSymbolAddress((void**)&we_h, wb_enc_hi);
    cudaGetSymbolAddress((void**)&we_l, wb_enc_lo);
    cudaGetSymbolAddress((void**)&wqkv_h, wb_qkv_hi);
    cudaGetSymbolAddress((void**)&wqkv_l, wb_qkv_lo);
    cudaGetSymbolAddress((void**)&wo_h, wb_o_hi);
    cudaGetSymbolAddress((void**)&wo_l, wb_o_lo);
    cudaGetSymbolAddress((void**)&f1h, wh_f1);
    cudaGetSymbolAddress((void**)&f2h, wh_f2);

    const int SMEM_DB = 2 * 4 * 128 * 20 * 4;   // 81920
    const int SMEM_FF = 6 * 128 * 272;          // 208896
    cudaFuncSetAttribute((const void*)gemm_db<DD, DD, false, false, false>, cudaFuncAttributeMaxDynamicSharedMemorySize, SMEM_DB);
    cudaFuncSetAttribute((const void*)gemm_db<DD, 384, false, false, false>, cudaFuncAttributeMaxDynamicSharedMemorySize, SMEM_DB);
    cudaFuncSetAttribute((const void*)gemm_db<DD, DD, false, true, false>, cudaFuncAttributeMaxDynamicSharedMemorySize, SMEM_DB);
    cudaFuncSetAttribute((const void*)ffn_fused, cudaFuncAttributeMaxDynamicSharedMemorySize, SMEM_FF);

    // weight split (once per call)
    split_w_kernel<<<(DD * DD + 255) / 256, 256>>>(enc_w2, we_h, we_l, DD, DD, DD * DD, DD, 0);
    split_w_qkv_kernel<<<(3 * LL * DD * DD + 255) / 256, 256>>>(wq, wk, wv, wqkv_h, wqkv_l);
    split_w_kernel<<<(LL * DD * DD + 255) / 256, 256>>>(wo, wo_h, wo_l, DD, DD, LL * DD * DD, DD, 0);
    split_w_h_kernel<<<(LL * DD * DFF + 255) / 256, 256>>>(ffn_w1, f1h, DD, DFF, LL * DD * DFF);
    split_w_h_kernel<<<(LL * DFF * DD + 255) / 256, 256>>>(ffn_w2, f2h, DFF, DD, LL * DFF * DD);

    // CSR build
    zero_cnt_kernel<<<(NN + 255) / 256, 256>>>();
    hist_kernel<<<(EE + 255) / 256, 256>>>(receivers);
    scan_kernel<<<1, 1024>>>();
    scatter_kernel<<<(EE + 255) / 256, 256>>>(senders, receivers);

    const int MT = (NN + 127) / 128;  // 391
    dim3 t128(MT, 1), t384(MT, 3);

    // encode
    gemm_small<<<(NN + 63) / 64, 256>>>(features, enc_w1, enc_b1, hhi, hlo, NN);
    gemm_db<DD, DD, false, false, false><<<t128, 256, SMEM_DB>>>(hhi, hlo, we_h, we_l, enc_b2, x, nullptr, nullptr, NN);

    for (int l = 0; l < LL; l++) {
        size_t o384 = (size_t)l * 384 * DD;
        size_t o128 = (size_t)l * DD * DD;
        size_t o512 = (size_t)l * DD * DFF;

        ln_kernel<<<(NN + 7) / 8, 256>>>(x, ln1_s + l * DD, ln1_b + l * DD, hhi, hlo, NN);
        gemm_db<DD, 384, false, false, false><<<t384, 256, SMEM_DB>>>(
            hhi, hlo, wqkv_h + o384, wqkv_l + o384, nullptr, qkv, nullptr, nullptr, NN);
        attn_kernel<<<(NN + 7) / 8, 256>>>();
        gemm_db<DD, DD, false, true, false><<<t128, 256, SMEM_DB>>>(
            hhi, hlo, wo_h + o128, wo_l + o128, nullptr, x, nullptr, nullptr, NN);

        // fused LN2 + FFN
        ffn_fused<<<MT, 256, SMEM_FF>>>(x, f1h + o512, f2h + o512,
                                        ffn_b1 + l * DFF, ffn_b2 + l * DD,
                                        ln2_s + l * DD, ln2_b + l * DD, x, NN);
    }

    decode_kernel<<<(NN + 3) / 4, 128>>>(x, dec_w1, dec_b1, dec_w2, dec_b2, out, NN);
}

// round 17
// speedup vs baseline: 1.0173x; 1.0173x over previous
#include <cuda_runtime.h>
#include <cuda_bf16.h>
#include <cuda_fp16.h>
#include <cstdint>
#include <math.h>

#define NN 50000
#define EE 600000
#define D_IN 16
#define DD 128
#define HH 4
#define DHH 32
#define LL 4
#define DFF 512
#define D_OUT 3

// ---------------- scratch ----------------
__device__ float g_x[NN * DD];
__device__ float g_qkv[NN * 384];
__device__ __nv_bfloat16 g_hhi[NN * DD], g_hlo[NN * DD];
__device__ int g_cnt[NN];
__device__ int g_cur[NN];
__device__ int g_rowptr[NN + 1];
__device__ int g_csr_snd[EE];

__device__ __nv_bfloat16 wb_enc_hi[DD * DD], wb_enc_lo[DD * DD];
__device__ __nv_bfloat16 wb_qkv_hi[LL * 384 * DD], wb_qkv_lo[LL * 384 * DD];
__device__ __nv_bfloat16 wb_o_hi[LL * DD * DD], wb_o_lo[LL * DD * DD];
__device__ __half wh_f1[LL * DD * DFF];
__device__ __half wh_f2[LL * DFF * DD];

// ---------------- helpers ----------------
__device__ __forceinline__ void hmma_bf16(float* c, const uint32_t* a, uint32_t b0, uint32_t b1) {
    asm volatile(
        "mma.sync.aligned.m16n8k16.row.col.f32.bf16.bf16.f32 "
        "{%0,%1,%2,%3}, {%4,%5,%6,%7}, {%8,%9}, {%0,%1,%2,%3};"
        : "+f"(c[0]), "+f"(c[1]), "+f"(c[2]), "+f"(c[3])
        : "r"(a[0]), "r"(a[1]), "r"(a[2]), "r"(a[3]), "r"(b0), "r"(b1));
}
__device__ __forceinline__ void hmma_f16(float* c, const uint32_t* a, uint32_t b0, uint32_t b1) {
    asm volatile(
        "mma.sync.aligned.m16n8k16.row.col.f32.f16.f16.f32 "
        "{%0,%1,%2,%3}, {%4,%5,%6,%7}, {%8,%9}, {%0,%1,%2,%3};"
        : "+f"(c[0]), "+f"(c[1]), "+f"(c[2]), "+f"(c[3])
        : "r"(a[0]), "r"(a[1]), "r"(a[2]), "r"(a[3]), "r"(b0), "r"(b1));
}
#define LDMX4(r0, r1, r2, r3, addr) \
    asm volatile("ldmatrix.sync.aligned.m8n8.x4.shared.b16 {%0,%1,%2,%3}, [%4];" \
                 : "=r"(r0), "=r"(r1), "=r"(r2), "=r"(r3) : "r"(addr))

__device__ __forceinline__ void split2(float x, float y, uint32_t& hi, uint32_t& lo) {
    __nv_bfloat16 hx = __float2bfloat16(x);
    __nv_bfloat16 hy = __float2bfloat16(y);
    __nv_bfloat16 lx = __float2bfloat16(x - __bfloat162float(hx));
    __nv_bfloat16 ly = __float2bfloat16(y - __bfloat162float(hy));
    __nv_bfloat162 hp = __halves2bfloat162(hx, hy);
    __nv_bfloat162 lp = __halves2bfloat162(lx, ly);
    hi = *(uint32_t*)&hp;
    lo = *(uint32_t*)&lp;
}
__device__ __forceinline__ void split2h(float x, float y, uint32_t& hi, uint32_t& lo) {
    __half hx = __float2half(x);
    __half hy = __float2half(y);
    __half lx = __float2half(x - __half2float(hx));
    __half ly = __float2half(y - __half2float(hy));
    __half2 hp = __halves2half2(hx, hy);
    __half2 lp = __halves2half2(lx, ly);
    hi = *(uint32_t*)&hp;
    lo = *(uint32_t*)&lp;
}
__device__ __forceinline__ uint32_t smem_u32(const void* p) {
    uint32_t a;
    asm("{ .reg .u64 t; cvta.to.shared.u64 t, %1; cvt.u32.u64 %0, t; }" : "=r"(a) : "l"(p));
    return a;
}
__device__ __forceinline__ void cp16(uint32_t dst, const void* src, int sz) {
    asm volatile("cp.async.ca.shared.global [%0], [%1], 16, %2;" :: "r"(dst), "l"(src), "r"(sz));
}

// ---------------- mega prologue: zero cnt + all weight splits in ONE launch ----------------
// Ranges: [0,NN) cnt zero | enc 16384 | qkv 3*65536 | wo 65536 | f1 262144 | f2 262144
__global__ void prologue_kernel(const float* __restrict__ enc_w2,
                                const float* __restrict__ Wq, const float* __restrict__ Wk,
                                const float* __restrict__ Wv, const float* __restrict__ Wo,
                                const float* __restrict__ F1, const float* __restrict__ F2) {
    int idx = blockIdx.x * blockDim.x + threadIdx.x;
    // zero cnt
    if (idx < NN) { g_cnt[idx] = 0; return; }
    idx -= NN;
    // enc_w2: K=128, M=128
    if (idx < DD * DD) {
        int r = idx / DD, c = idx - r * DD;
        float w = enc_w2[idx];
        __nv_bfloat16 h = __float2bfloat16(w);
        wb_enc_hi[c * DD + r] = h;
        wb_enc_lo[c * DD + r] = __float2bfloat16(w - __bfloat162float(h));
        return;
    }
    idx -= DD * DD;
    // qkv: 3 matrices, K=128, M=128, interleaved 384-col layout
    const int per = LL * DD * DD;
    if (idx < 3 * per) {
        int which = idx / per;
        int rem0 = idx - which * per;
        const float* W = (which == 0) ? Wq : (which == 1) ? Wk : Wv;
        int km = DD * DD;
        int mat = rem0 / km;
        int rem = rem0 - mat * km;
        int r = rem / DD, c = rem - r * DD;
        float w = W[rem0];
        __nv_bfloat16 h = __float2bfloat16(w);
        int dst = mat * (384 * DD) + (c + which * 128) * DD + r;
        wb_qkv_hi[dst] = h;
        wb_qkv_lo[dst] = __float2bfloat16(w - __bfloat162float(h));
        return;
    }
    idx -= 3 * per;
    // wo: K=128, M=128 per layer
    if (idx < per) {
        int km = DD * DD;
        int mat = idx / km;
        int rem = idx - mat * km;
        int r = rem / DD, c = rem - r * DD;
        float w = Wo[idx];
        __nv_bfloat16 h = __float2bfloat16(w);
        int dst = mat * km + c * DD + r;
        wb_o_hi[dst] = h;
        wb_o_lo[dst] = __float2bfloat16(w - __bfloat162float(h));
        return;
    }
    idx -= per;
    // f1: K=128, M=512 per layer -> fp16 transposed
    if (idx < LL * DD * DFF) {
        int km = DD * DFF;
        int mat = idx / km;
        int rem = idx - mat * km;
        int r = rem / DFF, c = rem - r * DFF;
        wh_f1[mat * km + c * DD + r] = __float2half(F1[idx]);
        return;
    }
    idx -= LL * DD * DFF;
    // f2: K=512, M=128 per layer -> fp16 transposed
    if (idx < LL * DFF * DD) {
        int km = DFF * DD;
        int mat = idx / km;
        int rem = idx - mat * km;
        int r = rem / DD, c = rem - r * DD;
        wh_f2[mat * km + c * DFF + r] = __float2half(F2[idx]);
    }
}

// ---------------- bf16x3 GEMM: cp.async double-buffer + ldmatrix ----------------
template <int K, int MOUT, bool RELU, bool ADD, bool OSPLIT>
__global__ void __launch_bounds__(256, 2) gemm_db(const __nv_bfloat16* __restrict__ Ahi,
                                                  const __nv_bfloat16* __restrict__ Alo,
                                                  const __nv_bfloat16* __restrict__ Bhi,
                                                  const __nv_bfloat16* __restrict__ Blo,
                                                  const float* __restrict__ bias,
                                                  float* __restrict__ C,
                                                  __nv_bfloat16* __restrict__ Ohi,
                                                  __nv_bfloat16* __restrict__ Olo, int n) {
    extern __shared__ uint32_t S[];
    constexpr int NCH = K / 32;
    constexpr int PL4 = 2560 * 4;
    constexpr int BUF4 = 10240 * 4;

    int tid = threadIdx.x;
    int l = tid & 31;
    int wm = (tid >> 5) & 3;
    int wn = tid >> 7;
    int row0 = blockIdx.x * 128, col0 = blockIdx.y * 128;
    uint32_t sbase = smem_u32(S);

    float acc[2][8][4];
#pragma unroll
    for (int a = 0; a < 2; a++)
#pragma unroll
        for (int b = 0; b < 8; b++)
#pragma unroll
            for (int c = 0; c < 4; c++) acc[a][b][c] = 0.f;

    auto stage = [&](int b, int k0) {
#pragma unroll
        for (int i = 0; i < 8; i++) {
            int plane = i >> 1;
            int cc = (i & 1) * 256 + tid;
            int row = cc >> 2, part = cc & 3;
            uint32_t daddr = sbase + (uint32_t)(b * BUF4 + plane * PL4 + (row * 20 + part * 4) * 4);
            if (plane < 2) {
                int grow = row0 + row;
                int ok = grow < n;
                const __nv_bfloat16* base = (plane == 0) ? Ahi : Alo;
                const void* src = base + (size_t)(ok ? grow : 0) * K + k0 + part * 8;
                cp16(daddr, src, ok ? 16 : 0);
            } else {
                const __nv_bfloat16* base = (plane == 2) ? Bhi : Blo;
                const void* src = base + (size_t)(col0 + row) * K + k0 + part * 8;
                cp16(daddr, src, 16);
            }
        }
    };

    const uint32_t aoff = (uint32_t)(((wm * 32 + (l & 15)) * 20 + (l >> 4) * 4) * 4);
    const uint32_t boff = (uint32_t)(((wn * 64 + (l & 7) + ((l >> 4) << 3)) * 20 + ((l >> 3) & 1) * 4) * 4);

    stage(0, 0);
    asm volatile("cp.async.commit_group;");

    for (int ch = 0; ch < NCH; ch++) {
        if (ch + 1 < NCH) {
            stage((ch + 1) & 1, (ch + 1) * 32);
            asm volatile("cp.async.commit_group;");
            asm volatile("cp.async.wait_group 1;");
        } else {
            asm volatile("cp.async.wait_group 0;");
        }
        __syncthreads();

        uint32_t base = sbase + (ch & 1) * BUF4;

#pragma unroll
        for (int ks = 0; ks < 2; ks++) {
            uint32_t kb = (uint32_t)(ks * 32);
            uint32_t ah[2][4], al[2][4];
            LDMX4(ah[0][0], ah[0][1], ah[0][2], ah[0][3], base + aoff + kb);
            LDMX4(ah[1][0], ah[1][1], ah[1][2], ah[1][3], base + aoff + 16 * 80 + kb);
            LDMX4(al[0][0], al[0][1], al[0][2], al[0][3], base + PL4 + aoff + kb);
            LDMX4(al[1][0], al[1][1], al[1][2], al[1][3], base + PL4 + aoff + 16 * 80 + kb);
#pragma unroll
            for (int tn2 = 0; tn2 < 4; tn2++) {
                uint32_t bh[4], bl[4];
                LDMX4(bh[0], bh[1], bh[2], bh[3], base + 2 * PL4 + boff + tn2 * 16 * 80 + kb);
                LDMX4(bl[0], bl[1], bl[2], bl[3], base + 3 * PL4 + boff + tn2 * 16 * 80 + kb);
#pragma unroll
                for (int sub = 0; sub < 2; sub++) {
                    int tn = 2 * tn2 + sub;
#pragma unroll
                    for (int tm = 0; tm < 2; tm++) {
                        hmma_bf16(acc[tm][tn], ah[tm], bh[2 * sub], bh[2 * sub + 1]);
                        hmma_bf16(acc[tm][tn], ah[tm], bl[2 * sub], bl[2 * sub + 1]);
                        hmma_bf16(acc[tm][tn], al[tm], bh[2 * sub], bh[2 * sub + 1]);
                    }
                }
            }
        }
        __syncthreads();
    }

#pragma unroll
    for (int tm = 0; tm < 2; tm++) {
#pragma unroll
        for (int tn = 0; tn < 8; tn++) {
            int row = row0 + wm * 32 + tm * 16 + (l >> 2);
            int col = col0 + wn * 64 + tn * 8 + (l & 3) * 2;
            float b0 = 0.f, b1 = 0.f;
            if (bias) { b0 = bias[col]; b1 = bias[col + 1]; }
#pragma unroll
            for (int half = 0; half < 2; half++) {
                int r = row + half * 8;
                if (r < n) {
                    float v0 = acc[tm][tn][half * 2 + 0] + b0;
                    float v1 = acc[tm][tn][half * 2 + 1] + b1;
                    if (RELU) { v0 = fmaxf(v0, 0.f); v1 = fmaxf(v1, 0.f); }
                    if (OSPLIT) {
                        uint32_t hi, lo;
                        split2(v0, v1, hi, lo);
                        *(uint32_t*)(Ohi + (size_t)r * MOUT + col) = hi;
                        *(uint32_t*)(Olo + (size_t)r * MOUT + col) = lo;
                    } else {
                        float2* cp = (float2*)(C + (size_t)r * MOUT + col);
                        if (ADD) {
                            float2 old = *cp;
                            v0 += old.x; v1 += old.y;
                        }
                        *cp = make_float2(v0, v1);
                    }
                }
            }
        }
    }
}

// ---------------- fused LN2 + FFN ----------------
__global__ void __launch_bounds__(256) ffn_fused(const float* __restrict__ X,
                                                 const __half* __restrict__ W1,
                                                 const __half* __restrict__ W2,
                                                 const float* __restrict__ b1,
                                                 const float* __restrict__ b2,
                                                 const float* __restrict__ lns,
                                                 const float* __restrict__ lnb,
                                                 float* __restrict__ C, int n) {
    extern __shared__ __half SH[];
    constexpr int RB = 272;
    const uint32_t sb = smem_u32(SH);
    const uint32_t oAhi = 0, oAlo = 128 * RB, oW1 = 2 * 128 * RB, oW2 = 3 * 128 * RB;
    const uint32_t oMhi = 4 * 128 * RB, oMlo = 5 * 128 * RB;
    const uint32_t oX = oMhi;

    int tid = threadIdx.x;
    int l = tid & 31;
    int wmw = (tid >> 5) & 3;
    int wn = tid >> 7;
    int wid = tid >> 5;
    int row0 = blockIdx.x * 128;

    float acc2[2][8][4];
#pragma unroll
    for (int a = 0; a < 2; a++)
#pragma unroll
        for (int b = 0; b < 8; b++)
#pragma unroll
            for (int c = 0; c < 4; c++) acc2[a][b][c] = 0.f;

#pragma unroll
    for (int i = 0; i < 16; i++) {
        int lin = i * 256 + tid;
        int row = lin >> 5, part = lin & 31;
        int grow = row0 + row;
        int ok = grow < n;
        const void* src = X + (size_t)(ok ? grow : 0) * DD + part * 4;
        cp16(sb + oX + row * 544 + part * 16, src, ok ? 16 : 0);
    }
    asm volatile("cp.async.commit_group;");

    auto stageW = [&](int c) {
#pragma unroll
        for (int i = 0; i < 16; i++) {
            int lin = i * 256 + tid;
            int which = lin >> 11;
            int rem = lin & 2047;
            int row = rem >> 4, part = rem & 15;
            if (which == 0) {
                const void* src = W1 + (size_t)(c * 128 + row) * DD + part * 8;
                cp16(sb + oW1 + row * RB + part * 16, src, 16);
            } else {
                const void* src = W2 + (size_t)row * DFF + c * 128 + part * 8;
                cp16(sb + oW2 + row * RB + part * 16, src, 16);
            }
        }
    };
    stageW(0);
    asm volatile("cp.async.commit_group;");

    asm volatile("cp.async.wait_group 1;");
    __syncthreads();

#pragma unroll
    for (int i = 0; i < 16; i++) {
        int row = wid * 16 + i;
        const float* xr = (const float*)((char*)SH + oX + row * 544);
        float4 v = *(const float4*)(xr + l * 4);
        float sum = v.x + v.y + v.z + v.w;
        float sq = v.x * v.x + v.y * v.y + v.z * v.z + v.w * v.w;
#pragma unroll
        for (int off = 16; off; off >>= 1) {
            sum += __shfl_xor_sync(0xffffffffu, sum, off);
            sq += __shfl_xor_sync(0xffffffffu, sq, off);
        }
        float mu = sum * (1.f / 128.f);
        float var = sq * (1.f / 128.f) - mu * mu;
        float rstd = rsqrtf(var + 1e-5f);
        float4 sv = *(const float4*)(lns + l * 4);
        float4 bv = *(const float4*)(lnb + l * 4);
        float o0 = (v.x - mu) * rstd * sv.x + bv.x;
        float o1 = (v.y - mu) * rstd * sv.y + bv.y;
        float o2 = (v.z - mu) * rstd * sv.z + bv.z;
        float o3 = (v.w - mu) * rstd * sv.w + bv.w;
        uint32_t h0, l0, h1, l1;
        split2h(o0, o1, h0, l0);
        split2h(o2, o3, h1, l1);
        *(uint32_t*)((char*)SH + oAhi + row * RB + l * 8) = h0;
        *(uint32_t*)((char*)SH + oAhi + row * RB + l * 8 + 4) = h1;
        *(uint32_t*)((char*)SH + oAlo + row * RB + l * 8) = l0;
        *(uint32_t*)((char*)SH + oAlo + row * RB + l * 8 + 4) = l1;
    }
    __syncthreads();

    const uint32_t aoff = (uint32_t)((wmw * 32 + (l & 15)) * RB + (l >> 4) * 16);
    const uint32_t boff = (uint32_t)((wn * 64 + (l & 7) + ((l >> 4) << 3)) * RB + ((l >> 3) & 1) * 16);

    for (int c = 0; c < 4; c++) {
        if (c > 0) {
            __syncthreads();
            stageW(c);
            asm volatile("cp.async.commit_group;");
        }
        asm volatile("cp.async.wait_group 0;");
        __syncthreads();

        float acc1[2][8][4];
#pragma unroll
        for (int a = 0; a < 2; a++)
#pragma unroll
            for (int b = 0; b < 8; b++)
#pragma unroll
                for (int q = 0; q < 4; q++) acc1[a][b][q] = 0.f;

#pragma unroll
        for (int ks = 0; ks < 8; ks++) {
            uint32_t kb = (uint32_t)(ks * 32);
            uint32_t ah[2][4], al[2][4];
            LDMX4(ah[0][0], ah[0][1], ah[0][2], ah[0][3], sb + oAhi + aoff + kb);
            LDMX4(ah[1][0], ah[1][1], ah[1][2], ah[1][3], sb + oAhi + aoff + 16 * RB + kb);
            LDMX4(al[0][0], al[0][1], al[0][2], al[0][3], sb + oAlo + aoff + kb);
            LDMX4(al[1][0], al[1][1], al[1][2], al[1][3], sb + oAlo + aoff + 16 * RB + kb);
#pragma unroll
            for (int tn2 = 0; tn2 < 4; tn2++) {
                uint32_t bb[4];
                LDMX4(bb[0], bb[1], bb[2], bb[3], sb + oW1 + boff + tn2 * 16 * RB + kb);
#pragma unroll
                for (int sub = 0; sub < 2; sub++) {
                    int tn = 2 * tn2 + sub;
#pragma unroll
                    for (int tm = 0; tm < 2; tm++) {
                        hmma_f16(acc1[tm][tn], ah[tm], bb[2 * sub], bb[2 * sub + 1]);
                        hmma_f16(acc1[tm][tn], al[tm], bb[2 * sub], bb[2 * sub + 1]);
                    }
                }
            }
        }

#pragma unroll
        for (int tm = 0; tm < 2; tm++) {
#pragma unroll
            for (int tn = 0; tn < 8; tn++) {
                int rloc = wmw * 32 + tm * 16 + (l >> 2);
                int cloc = wn * 64 + tn * 8 + (l & 3) * 2;
                float bb0 = b1[c * 128 + cloc], bb1 = b1[c * 128 + cloc + 1];
#pragma unroll
                for (int half = 0; half < 2; half++) {
                    int rr = rloc + half * 8;
                    float v0 = fmaxf(acc1[tm][tn][half * 2 + 0] + bb0, 0.f);
                    float v1 = fmaxf(acc1[tm][tn][half * 2 + 1] + bb1, 0.f);
                    uint32_t hi, lo;
                    split2h(v0, v1, hi, lo);
                    *(uint32_t*)((char*)SH + oMhi + rr * RB + cloc * 2) = hi;
                    *(uint32_t*)((char*)SH + oMlo + rr * RB + cloc * 2) = lo;
                }
            }
        }
        __syncthreads();

#pragma unroll
        for (int ks = 0; ks < 8; ks++) {
            uint32_t kb = (uint32_t)(ks * 32);
            uint32_t mh[2][4], ml[2][4];
            LDMX4(mh[0][0], mh[0][1], mh[0][2], mh[0][3], sb + oMhi + aoff + kb);
            LDMX4(mh[1][0], mh[1][1], mh[1][2], mh[1][3], sb + oMhi + aoff + 16 * RB + kb);
            LDMX4(ml[0][0], ml[0][1], ml[0][2], ml[0][3], sb + oMlo + aoff + kb);
            LDMX4(ml[1][0], ml[1][1], ml[1][2], ml[1][3], sb + oMlo + aoff + 16 * RB + kb);
#pragma unroll
            for (int tn2 = 0; tn2 < 4; tn2++) {
                uint32_t bb[4];
                LDMX4(bb[0], bb[1], bb[2], bb[3], sb + oW2 + boff + tn2 * 16 * RB + kb);
#pragma unroll
                for (int sub = 0; sub < 2; sub++) {
                    int tn = 2 * tn2 + sub;
#pragma unroll
                    for (int tm = 0; tm < 2; tm++) {
                        hmma_f16(acc2[tm][tn], mh[tm], bb[2 * sub], bb[2 * sub + 1]);
                        hmma_f16(acc2[tm][tn], ml[tm], bb[2 * sub], bb[2 * sub + 1]);
                    }
                }
            }
        }
    }

#pragma unroll
    for (int tm = 0; tm < 2; tm++) {
#pragma unroll
        for (int tn = 0; tn < 8; tn++) {
            int row = row0 + wmw * 32 + tm * 16 + (l >> 2);
            int col = wn * 64 + tn * 8 + (l & 3) * 2;
            float bb0 = b2[col], bb1 = b2[col + 1];
#pragma unroll
            for (int half = 0; half < 2; half++) {
                int r = row + half * 8;
                if (r < n) {
                    float2* cp = (float2*)(C + (size_t)r * DD + col);
                    float2 old = *cp;
                    *cp = make_float2(acc2[tm][tn][half * 2 + 0] + bb0 + old.x,
                                      acc2[tm][tn][half * 2 + 1] + bb1 + old.y);
                }
            }
        }
    }
}

// ---------------- small fp32 GEMM (encoder K=16) -> split bf16 out ----------------
__global__ void __launch_bounds__(256) gemm_small(const float* __restrict__ A,
                                                  const float* __restrict__ W,
                                                  const float* __restrict__ bias,
                                                  __nv_bfloat16* __restrict__ Ohi,
                                                  __nv_bfloat16* __restrict__ Olo, int n) {
    constexpr int K = D_IN, MOUT = DD, BM = 64, BK = 16, TM = 8, TN = 4;
    __shared__ float As[BK][BM + 4];
    __shared__ float Ws[BK][MOUT];
    int row0 = blockIdx.x * BM;
    int tid = threadIdx.x;
    int tx = tid & 31, ty = tid >> 5;
    float acc[TM][TN];
#pragma unroll
    for (int i = 0; i < TM; i++)
#pragma unroll
        for (int j = 0; j < TN; j++) acc[i][j] = 0.f;
    int a_row = tid >> 2, a_kq = (tid & 3) * 4;
    {
        float4 av = make_float4(0.f, 0.f, 0.f, 0.f);
        int grow = row0 + a_row;
        if (grow < n) av = *(const float4*)(A + (size_t)grow * K + a_kq);
        As[a_kq + 0][a_row] = av.x;
        As[a_kq + 1][a_row] = av.y;
        As[a_kq + 2][a_row] = av.z;
        As[a_kq + 3][a_row] = av.w;
#pragma unroll
        for (int i = 0; i < 2; i++) {
            int lin = tid + i * 256;
            int wk = lin >> 5;
            int wc = (lin & 31) * 4;
            *(float4*)&Ws[wk][wc] = *(const float4*)(W + (size_t)wk * MOUT + wc);
        }
        __syncthreads();
#pragma unroll
        for (int kk = 0; kk < BK; kk++) {
            float a[TM], w[TN];
            *(float4*)&a[0] = *(float4*)&As[kk][ty * TM];
            *(float4*)&a[4] = *(float4*)&As[kk][ty * TM + 4];
            *(float4*)&w[0] = *(float4*)&Ws[kk][tx * TN];
#pragma unroll
            for (int i = 0; i < TM; i++)
#pragma unroll
                for (int j = 0; j < TN; j++) acc[i][j] += a[i] * w[j];
        }
    }
#pragma unroll
    for (int i = 0; i < TM; i++) {
        int row = row0 + ty * TM + i;
        if (row < n) {
            float v0 = fmaxf(acc[i][0] + bias[tx * TN + 0], 0.f);
            float v1 = fmaxf(acc[i][1] + bias[tx * TN + 1], 0.f);
            float v2 = fmaxf(acc[i][2] + bias[tx * TN + 2], 0.f);
            float v3 = fmaxf(acc[i][3] + bias[tx * TN + 3], 0.f);
            uint32_t h0, l0, h1, l1;
            split2(v0, v1, h0, l0);
            split2(v2, v3, h1, l1);
            *(uint2*)(Ohi + (size_t)row * MOUT + tx * TN) = make_uint2(h0, h1);
            *(uint2*)(Olo + (size_t)row * MOUT + tx * TN) = make_uint2(l0, l1);
        }
    }
}

// ---------------- LayerNorm -> split bf16 out ----------------
__global__ void ln_kernel(const float* __restrict__ x, const float* __restrict__ s,
                          const float* __restrict__ b, __nv_bfloat16* __restrict__ Ohi,
                          __nv_bfloat16* __restrict__ Olo, int n) {
    int row = blockIdx.x * 8 + (threadIdx.x >> 5);
    if (row >= n) return;
    int lane = threadIdx.x & 31;
    float4 v = *(const float4*)(x + (size_t)row * DD + lane * 4);
    float sum = v.x + v.y + v.z + v.w;
    float sq = v.x * v.x + v.y * v.y + v.z * v.z + v.w * v.w;
#pragma unroll
    for (int off = 16; off; off >>= 1) {
        sum += __shfl_xor_sync(0xffffffffu, sum, off);
        sq += __shfl_xor_sync(0xffffffffu, sq, off);
    }
    float mu = sum * (1.f / 128.f);
    float var = sq * (1.f / 128.f) - mu * mu;
    float rstd = rsqrtf(var + 1e-5f);
    float4 sv = *(const float4*)(s + lane * 4);
    float4 bv = *(const float4*)(b + lane * 4);
    float o0 = (v.x - mu) * rstd * sv.x + bv.x;
    float o1 = (v.y - mu) * rstd * sv.y + bv.y;
    float o2 = (v.z - mu) * rstd * sv.z + bv.z;
    float o3 = (v.w - mu) * rstd * sv.w + bv.w;
    uint32_t h0, l0, h1, l1;
    split2(o0, o1, h0, l0);
    split2(o2, o3, h1, l1);
    *(uint2*)(Ohi + (size_t)row * DD + lane * 4) = make_uint2(h0, h1);
    *(uint2*)(Olo + (size_t)row * DD + lane * 4) = make_uint2(l0, l1);
}

// ---------------- CSR build ----------------
__global__ void hist_kernel(const int* __restrict__ receivers) {
    int e = blockIdx.x * blockDim.x + threadIdx.x;
    if (e < EE) atomicAdd(&g_cnt[receivers[e]], 1);
}
__global__ void scan_kernel() {
    __shared__ int warp_sums[32];
    __shared__ int s_carry;
    int lane = threadIdx.x & 31;
    int wid = threadIdx.x >> 5;
    if (threadIdx.x == 0) s_carry = 0;
    __syncthreads();
    for (int base = 0; base < NN; base += 1024) {
        int i = base + threadIdx.x;
        int v = (i < NN) ? g_cnt[i] : 0;
        int incl = v;
#pragma unroll
        for (int off = 1; off < 32; off <<= 1) {
            int t = __shfl_up_sync(0xffffffffu, incl, off);
            if (lane >= off) incl += t;
        }
        if (lane == 31) warp_sums[wid] = incl;
        __syncthreads();
        if (wid == 0) {
            int ws = warp_sums[lane];
            int wincl = ws;
#pragma unroll
            for (int off = 1; off < 32; off <<= 1) {
                int t = __shfl_up_sync(0xffffffffu, wincl, off);
                if (lane >= off) wincl += t;
            }
            warp_sums[lane] = wincl - ws;
        }
        __syncthreads();
        int total_incl = s_carry + warp_sums[wid] + incl;
        if (i < NN) {
            g_rowptr[i + 1] = total_incl;
            g_cur[i] = total_incl - v;
        }
        __syncthreads();
        if (threadIdx.x == 1023) s_carry = total_incl;
        __syncthreads();
    }
    if (threadIdx.x == 0) g_rowptr[0] = 0;
}
__global__ void scatter_kernel(const int* __restrict__ senders,
                               const int* __restrict__ receivers) {
    int e = blockIdx.x * blockDim.x + threadIdx.x;
    if (e >= EE) return;
    int pos = atomicAdd(&g_cur[receivers[e]], 1);
    g_csr_snd[pos] = senders[e];
}

// ---------------- fused sparse attention: warp per node, software-pipelined ----------------
__global__ void attn_kernel() {
    int warp = (blockIdx.x * blockDim.x + threadIdx.x) >> 5;
    if (warp >= NN) return;
    int lane = threadIdx.x & 31;
    int node = warp;
    int l4 = lane * 4;

    float4 q4 = *(const float4*)(g_qkv + (size_t)node * 384 + l4);
    int beg = g_rowptr[node], end = g_rowptr[node + 1];

    float m = -INFINITY, den = 0.f;
    float4 acc = make_float4(0.f, 0.f, 0.f, 0.f);

    if (beg < end) {
        int snd = g_csr_snd[beg];
        const float* kp = g_qkv + (size_t)snd * 384 + 128;
        float4 k4 = *(const float4*)(kp + l4);
        float4 v4 = *(const float4*)(kp + 128 + l4);
        for (int j = beg; j < end; j++) {
            int snd_n = (j + 1 < end) ? g_csr_snd[j + 1] : snd;
            const float* kpn = g_qkv + (size_t)snd_n * 384 + 128;
            float4 k4n = *(const float4*)(kpn + l4);
            float4 v4n = *(const float4*)(kpn + 128 + l4);

            float d = q4.x * k4.x + q4.y * k4.y + q4.z * k4.z + q4.w * k4.w;
            d += __shfl_xor_sync(0xffffffffu, d, 1);
            d += __shfl_xor_sync(0xffffffffu, d, 2);
            d += __shfl_xor_sync(0xffffffffu, d, 4);
            float s = d * 0.17677669529663687f;
            float nm = fmaxf(m, s);
            float alpha = __expf(m - nm);
            float a = __expf(s - nm);
            den = den * alpha + a;
            acc.x = acc.x * alpha + a * v4.x;
            acc.y = acc.y * alpha + a * v4.y;
            acc.z = acc.z * alpha + a * v4.z;
            acc.w = acc.w * alpha + a * v4.w;
            m = nm;
            k4 = k4n; v4 = v4n;
        }
    }
    float inv = 1.f / (den + 1e-9f);
    uint32_t h0, l0, h1, l1;
    split2(acc.x * inv, acc.y * inv, h0, l0);
    split2(acc.z * inv, acc.w * inv, h1, l1);
    *(uint2*)(g_hhi + (size_t)node * DD + l4) = make_uint2(h0, h1);
    *(uint2*)(g_hlo + (size_t)node * DD + l4) = make_uint2(l0, l1);
}

// ---------------- decoder ----------------
__global__ void decode_kernel(const float* __restrict__ x, const float* __restrict__ w1,
                              const float* __restrict__ b1, const float* __restrict__ w2,
                              const float* __restrict__ b2, float* __restrict__ out, int n) {
    int row = blockIdx.x * 4 + (threadIdx.x >> 5);
    if (row >= n) return;
    int lane = threadIdx.x & 31;
    float4 xr = *(const float4*)(x + (size_t)row * DD + lane * 4);
    float t[3];
#pragma unroll
    for (int o = 0; o < 3; o++) {
        float p = xr.x * w1[(lane * 4 + 0) * 3 + o] + xr.y * w1[(lane * 4 + 1) * 3 + o] +
                  xr.z * w1[(lane * 4 + 2) * 3 + o] + xr.w * w1[(lane * 4 + 3) * 3 + o];
#pragma unroll
        for (int off = 16; off; off >>= 1) p += __shfl_down_sync(0xffffffffu, p, off);
        t[o] = p;
    }
    if (lane == 0) {
        float r0 = fmaxf(t[0] + b1[0], 0.f);
        float r1 = fmaxf(t[1] + b1[1], 0.f);
        float r2 = fmaxf(t[2] + b1[2], 0.f);
#pragma unroll
        for (int o2 = 0; o2 < 3; o2++)
            out[row * 3 + o2] = r0 * w2[0 * 3 + o2] + r1 * w2[1 * 3 + o2] + r2 * w2[2 * 3 + o2] + b2[o2];
    }
}

// ---------------- host ----------------
extern "C" void kernel_launch(void* const* d_in, const int* in_sizes, int n_in,
                              void* d_out, int out_size) {
    const float* features = (const float*)d_in[0];
    const int* senders = (const int*)d_in[1];
    const int* receivers = (const int*)d_in[2];
    const float* enc_w1 = (const float*)d_in[3];
    const float* enc_b1 = (const float*)d_in[4];
    const float* enc_w2 = (const float*)d_in[5];
    const float* enc_b2 = (const float*)d_in[6];
    const float* wq = (const float*)d_in[7];
    const float* wk = (const float*)d_in[8];
    const float* wv = (const float*)d_in[9];
    const float* wo = (const float*)d_in[10];
    const float* ln1_s = (const float*)d_in[11];
    const float* ln1_b = (const float*)d_in[12];
    const float* ffn_w1 = (const float*)d_in[13];
    const float* ffn_b1 = (const float*)d_in[14];
    const float* ffn_w2 = (const float*)d_in[15];
    const float* ffn_b2 = (const float*)d_in[16];
    const float* ln2_s = (const float*)d_in[17];
    const float* ln2_b = (const float*)d_in[18];
    const float* dec_w1 = (const float*)d_in[19];
    const float* dec_b1 = (const float*)d_in[20];
    const float* dec_w2 = (const float*)d_in[21];
    const float* dec_b2 = (const float*)d_in[22];
    float* out = (float*)d_out;

    float* x;    cudaGetSymbolAddress((void**)&x, g_x);
    float* qkv;  cudaGetSymbolAddress((void**)&qkv, g_qkv);
    __nv_bfloat16 *hhi, *hlo;
    cudaGetSymbolAddress((void**)&hhi, g_hhi);
    cudaGetSymbolAddress((void**)&hlo, g_hlo);
    __nv_bfloat16 *we_h, *we_l, *wqkv_h, *wqkv_l, *wo_h, *wo_l;
    __half *f1h, *f2h;
    cudaGetSymbolAddress((void**)&we_h, wb_enc_hi);
    cudaGetSymbolAddress((void**)&we_l, wb_enc_lo);
    cudaGetSymbolAddress((void**)&wqkv_h, wb_qkv_hi);
    cudaGetSymbolAddress((void**)&wqkv_l, wb_qkv_lo);
    cudaGetSymbolAddress((void**)&wo_h, wb_o_hi);
    cudaGetSymbolAddress((void**)&wo_l, wb_o_lo);
    cudaGetSymbolAddress((void**)&f1h, wh_f1);
    cudaGetSymbolAddress((void**)&f2h, wh_f2);

    const int SMEM_DB = 2 * 4 * 128 * 20 * 4;   // 81920
    const int SMEM_FF = 6 * 128 * 272;          // 208896
    cudaFuncSetAttribute((const void*)gemm_db<DD, DD, false, false, false>, cudaFuncAttributeMaxDynamicSharedMemorySize, SMEM_DB);
    cudaFuncSetAttribute((const void*)gemm_db<DD, 384, false, false, false>, cudaFuncAttributeMaxDynamicSharedMemorySize, SMEM_DB);
    cudaFuncSetAttribute((const void*)gemm_db<DD, DD, false, true, false>, cudaFuncAttributeMaxDynamicSharedMemorySize, SMEM_DB);
    cudaFuncSetAttribute((const void*)ffn_fused, cudaFuncAttributeMaxDynamicSharedMemorySize, SMEM_FF);

    // mega prologue: zero cnt + all 5 weight splits in one launch
    const int PRO_TOTAL = NN + DD * DD + 3 * LL * DD * DD + LL * DD * DD + LL * DD * DFF + LL * DFF * DD;
    prologue_kernel<<<(PRO_TOTAL + 255) / 256, 256>>>(enc_w2, wq, wk, wv, wo, ffn_w1, ffn_w2);

    // CSR build (depends on zeroed cnt)
    hist_kernel<<<(EE + 255) / 256, 256>>>(receivers);
    scan_kernel<<<1, 1024>>>();
    scatter_kernel<<<(EE + 255) / 256, 256>>>(senders, receivers);

    const int MT = (NN + 127) / 128;  // 391
    dim3 t128(MT, 1), t384(MT, 3);

    // encode
    gemm_small<<<(NN + 63) / 64, 256>>>(features, enc_w1, enc_b1, hhi, hlo, NN);
    gemm_db<DD, DD, false, false, false><<<t128, 256, SMEM_DB>>>(hhi, hlo, we_h, we_l, enc_b2, x, nullptr, nullptr, NN);

    for (int l = 0; l < LL; l++) {
        size_t o384 = (size_t)l * 384 * DD;
        size_t o128 = (size_t)l * DD * DD;
        size_t o512 = (size_t)l * DD * DFF;

        ln_kernel<<<(NN + 7) / 8, 256>>>(x, ln1_s + l * DD, ln1_b + l * DD, hhi, hlo, NN);
        gemm_db<DD, 384, false, false, false><<<t384, 256, SMEM_DB>>>(
            hhi, hlo, wqkv_h + o384, wqkv_l + o384, nullptr, qkv, nullptr, nullptr, NN);
        attn_kernel<<<(NN + 7) / 8, 256>>>();
        gemm_db<DD, DD, false, true, false><<<t128, 256, SMEM_DB>>>(
            hhi, hlo, wo_h + o128, wo_l + o128, nullptr, x, nullptr, nullptr, NN);

        // fused LN2 + FFN
        ffn_fused<<<MT, 256, SMEM_FF>>>(x, f1h + o512, f2h + o512,
                                        ffn_b1 + l * DFF, ffn_b2 + l * DD,
                                        ln2_s + l * DD, ln2_b + l * DD, x, NN);
    }

    decode_kernel<<<(NN + 3) / 4, 128>>>(x, dec_w1, dec_b1, dec_w2, dec_b2, out, NN);
}